// round 1
// baseline (speedup 1.0000x reference)
#include <cuda_runtime.h>
#include <cuda_bf16.h>
#include <math.h>

// ---------------------------------------------------------------------------
// SwinTransformerBlock: B=32, H=W=56, C=256, NH=8, hd=32, WS=7, SS=3
// M = 32*56*56 = 100352 tokens, 2048 windows of N=49.
// Pipeline:
//   ln1+shift+partition -> qkv gemm -> windowed attention -> proj gemm
//   (+reverse/unshift/residual) -> ln2 -> fc1+gelu -> fc2+residual -> out
// ---------------------------------------------------------------------------

#define M_TOK   100352      // 32*3136
#define C_DIM   256
#define NHEADS  8
#define HDIM    32
#define NWIN    2048        // 32 * 64
#define NSEQ    49

// scratch (device globals; no allocation allowed)
__device__ float g_zw[(size_t)M_TOK * C_DIM];      // LN1+shift+partition
__device__ float g_qkv[(size_t)M_TOK * 768];       // qkv projection
__device__ float g_o[(size_t)M_TOK * C_DIM];       // attention output (window order)
__device__ float g_x2[(size_t)M_TOK * C_DIM];      // residual after proj (token order)
__device__ float g_h[(size_t)M_TOK * C_DIM];       // LN2 output
__device__ float g_fc1[(size_t)M_TOK * 1024];      // fc1+gelu output

// ---------------------------------------------------------------------------
// LayerNorm (one block per token, 256 threads). shifted=1 applies the
// cyclic-shift + window-partition gather: output row t is in window order.
// ---------------------------------------------------------------------------
__global__ void ln_kernel(const float* __restrict__ x,
                          const float* __restrict__ gamma,
                          const float* __restrict__ beta,
                          float* __restrict__ out,
                          int shifted)
{
    int t = blockIdx.x;
    int src;
    if (shifted) {
        int wi  = t / NSEQ;
        int pos = t - wi * NSEQ;
        int b    = wi >> 6;
        int wrem = wi & 63;
        int hs = (wrem >> 3) * 7 + pos / 7;
        int ws = (wrem & 7) * 7 + pos % 7;
        int sh = hs + 3; if (sh >= 56) sh -= 56;
        int sw = ws + 3; if (sw >= 56) sw -= 56;
        src = b * 3136 + sh * 56 + sw;
    } else {
        src = t;
    }
    int c = threadIdx.x;
    float v = x[(size_t)src * C_DIM + c];
    float s = v, s2 = v * v;
    #pragma unroll
    for (int off = 16; off; off >>= 1) {
        s  += __shfl_xor_sync(0xffffffffu, s,  off);
        s2 += __shfl_xor_sync(0xffffffffu, s2, off);
    }
    __shared__ float wsum[8], wsum2[8];
    int w = threadIdx.x >> 5, lane = threadIdx.x & 31;
    if (lane == 0) { wsum[w] = s; wsum2[w] = s2; }
    __syncthreads();
    float ts = 0.f, ts2 = 0.f;
    #pragma unroll
    for (int i = 0; i < 8; i++) { ts += wsum[i]; ts2 += wsum2[i]; }
    float mean = ts * (1.f / 256.f);
    float var  = ts2 * (1.f / 256.f) - mean * mean;
    float r = rsqrtf(var + 1e-6f);
    out[(size_t)t * C_DIM + c] = (v - mean) * r * gamma[c] + beta[c];
}

// ---------------------------------------------------------------------------
// Tiled SGEMM: C[M,Nc] = A[M,K] @ W[K,Nc] (+ epilogue)
// BM=128, BN=64, BK=16, 256 threads, 8x4 register microtile.
// EPI 0: +bias                      (qkv)
// EPI 1: gelu(+bias)                (fc1)
// EPI 2: residual[m] + bias + acc   (fc2 -> d_out)
// EPI 3: proj: scatter row m via window-reverse+unshift, + x residual
// ---------------------------------------------------------------------------
#define BM 128
#define BN 64
#define BK 16

template<int EPI>
__global__ void gemm_kernel(const float* __restrict__ A,
                            const float* __restrict__ W,
                            const float* __restrict__ bias,
                            const float* __restrict__ residual,
                            float* __restrict__ out,
                            int Nc, int K)
{
    __shared__ float As[BK][BM];
    __shared__ float Bs[BK][BN];

    int bm = blockIdx.x * BM;
    int bn = blockIdx.y * BN;
    int tid = threadIdx.x;
    int tx = tid & 15;       // 16 col groups (4 cols each)
    int ty = tid >> 4;       // 16 row groups (8 rows each)

    float acc[8][4];
    #pragma unroll
    for (int i = 0; i < 8; i++)
        #pragma unroll
        for (int j = 0; j < 4; j++) acc[i][j] = 0.f;

    for (int k0 = 0; k0 < K; k0 += BK) {
        // A tile: 128x16, float4 loads, store transposed
        #pragma unroll
        for (int l = 0; l < 2; l++) {
            int q = tid + l * 256;
            int row = q >> 2;
            int kk  = (q & 3) * 4;
            float4 av = *(const float4*)(A + (size_t)(bm + row) * K + k0 + kk);
            As[kk + 0][row] = av.x;
            As[kk + 1][row] = av.y;
            As[kk + 2][row] = av.z;
            As[kk + 3][row] = av.w;
        }
        // B tile: 16x64, one float4 per thread
        {
            int row = tid >> 4;
            int col = (tid & 15) * 4;
            float4 bv = *(const float4*)(W + (size_t)(k0 + row) * Nc + bn + col);
            *(float4*)&Bs[row][col] = bv;
        }
        __syncthreads();
        #pragma unroll
        for (int k = 0; k < BK; k++) {
            float a[8], bv[4];
            *(float4*)&a[0] = *(const float4*)&As[k][ty * 8];
            *(float4*)&a[4] = *(const float4*)&As[k][ty * 8 + 4];
            *(float4*)&bv[0] = *(const float4*)&Bs[k][tx * 4];
            #pragma unroll
            for (int i = 0; i < 8; i++)
                #pragma unroll
                for (int j = 0; j < 4; j++)
                    acc[i][j] = fmaf(a[i], bv[j], acc[i][j]);
        }
        __syncthreads();
    }

    int ncol = bn + tx * 4;
    float4 b4 = *(const float4*)(bias + ncol);

    #pragma unroll
    for (int i = 0; i < 8; i++) {
        int m = bm + ty * 8 + i;
        float4 r4;
        r4.x = acc[i][0] + b4.x;
        r4.y = acc[i][1] + b4.y;
        r4.z = acc[i][2] + b4.z;
        r4.w = acc[i][3] + b4.w;
        if (EPI == 0) {
            *(float4*)(out + (size_t)m * Nc + ncol) = r4;
        } else if (EPI == 1) {
            // exact GELU: x * 0.5 * (1 + erf(x/sqrt(2)))
            r4.x = r4.x * 0.5f * (1.f + erff(r4.x * 0.70710678118654752f));
            r4.y = r4.y * 0.5f * (1.f + erff(r4.y * 0.70710678118654752f));
            r4.z = r4.z * 0.5f * (1.f + erff(r4.z * 0.70710678118654752f));
            r4.w = r4.w * 0.5f * (1.f + erff(r4.w * 0.70710678118654752f));
            *(float4*)(out + (size_t)m * Nc + ncol) = r4;
        } else if (EPI == 2) {
            float4 x4 = *(const float4*)(residual + (size_t)m * Nc + ncol);
            r4.x += x4.x; r4.y += x4.y; r4.z += x4.z; r4.w += x4.w;
            *(float4*)(out + (size_t)m * Nc + ncol) = r4;
        } else { // EPI == 3: window-reverse + unshift scatter + residual from x
            int wi  = m / NSEQ;
            int pos = m - wi * NSEQ;
            int b    = wi >> 6;
            int wrem = wi & 63;
            int hs = (wrem >> 3) * 7 + pos / 7;
            int ws = (wrem & 7) * 7 + pos % 7;
            int dh = hs + 3; if (dh >= 56) dh -= 56;
            int dw = ws + 3; if (dw >= 56) dw -= 56;
            int dst = b * 3136 + dh * 56 + dw;
            float4 x4 = *(const float4*)(residual + (size_t)dst * Nc + ncol);
            r4.x += x4.x; r4.y += x4.y; r4.z += x4.z; r4.w += x4.w;
            *(float4*)(out + (size_t)dst * Nc + ncol) = r4;
        }
    }
}

// ---------------------------------------------------------------------------
// Windowed attention: one block per (window, head). N=49, hd=32.
// ---------------------------------------------------------------------------
__global__ void attn_kernel(const float* __restrict__ qkv,
                            const float* __restrict__ attn_mask,
                            const float* __restrict__ rel_table,
                            const int*   __restrict__ rel_idx,
                            const float* __restrict__ temperature,
                            float* __restrict__ o)
{
    int wi = blockIdx.x;   // 0..2047
    int h  = blockIdx.y;   // 0..7
    __shared__ float qs[49][33], ks[49][33], vs[49][33];
    __shared__ float S[49][50];
    int tid = threadIdx.x; // 256

    float scale = expf(temperature[0]);
    const float* base = qkv + (size_t)wi * NSEQ * 768 + h * HDIM;

    for (int idx = tid; idx < NSEQ * HDIM; idx += 256) {
        int n = idx >> 5, d = idx & 31;
        const float* r = base + n * 768 + d;
        qs[n][d] = r[0];
        ks[n][d] = r[256];
        vs[n][d] = r[512];
    }
    __syncthreads();

    int mask_base = (wi & 63) * (NSEQ * NSEQ);
    for (int idx = tid; idx < NSEQ * NSEQ; idx += 256) {
        int n = idx / NSEQ, m = idx - n * NSEQ;
        float dot = 0.f;
        #pragma unroll
        for (int d = 0; d < HDIM; d++) dot = fmaf(qs[n][d], ks[m][d], dot);
        float s = dot * scale;
        if (n == m) s = -3.402823466e38f;          // finfo(f32).min diag mask
        s += rel_table[rel_idx[idx] * NHEADS + h]; // relative position bias
        s += attn_mask[mask_base + idx];           // shift mask
        S[n][m] = s;
    }
    __syncthreads();

    if (tid < NSEQ) {
        int n = tid;
        float mx = -3.402823466e38f;
        #pragma unroll
        for (int m = 0; m < NSEQ; m++) mx = fmaxf(mx, S[n][m]);
        float sum = 0.f;
        #pragma unroll
        for (int m = 0; m < NSEQ; m++) { float e = expf(S[n][m] - mx); S[n][m] = e; sum += e; }
        float inv = 1.f / sum;
        #pragma unroll
        for (int m = 0; m < NSEQ; m++) S[n][m] *= inv;
    }
    __syncthreads();

    for (int idx = tid; idx < NSEQ * HDIM; idx += 256) {
        int n = idx >> 5, d = idx & 31;
        float a = 0.f;
        #pragma unroll
        for (int m = 0; m < NSEQ; m++) a = fmaf(S[n][m], vs[m][d], a);
        o[(size_t)(wi * NSEQ + n) * C_DIM + h * HDIM + d] = a;
    }
}

// ---------------------------------------------------------------------------
// Launch
// ---------------------------------------------------------------------------
extern "C" void kernel_launch(void* const* d_in, const int* in_sizes, int n_in,
                              void* d_out, int out_size)
{
    const float* x        = (const float*)d_in[0];
    const float* attn_msk = (const float*)d_in[1];
    const float* norm1_g  = (const float*)d_in[2];
    const float* norm1_b  = (const float*)d_in[3];
    const float* qkv_w    = (const float*)d_in[4];
    const float* qkv_b    = (const float*)d_in[5];
    const float* temp     = (const float*)d_in[6];
    const float* rel_tab  = (const float*)d_in[7];
    const float* proj_w   = (const float*)d_in[8];
    const float* proj_b   = (const float*)d_in[9];
    const float* norm2_g  = (const float*)d_in[10];
    const float* norm2_b  = (const float*)d_in[11];
    const float* fc1_w    = (const float*)d_in[12];
    const float* fc1_b    = (const float*)d_in[13];
    const float* fc2_w    = (const float*)d_in[14];
    const float* fc2_b    = (const float*)d_in[15];
    const int*   rel_idx  = (const int*)d_in[16];
    float* out = (float*)d_out;

    float *zw, *qkv, *o, *x2, *hbuf, *fc1;
    cudaGetSymbolAddress((void**)&zw,   g_zw);
    cudaGetSymbolAddress((void**)&qkv,  g_qkv);
    cudaGetSymbolAddress((void**)&o,    g_o);
    cudaGetSymbolAddress((void**)&x2,   g_x2);
    cudaGetSymbolAddress((void**)&hbuf, g_h);
    cudaGetSymbolAddress((void**)&fc1,  g_fc1);

    // 1. LN1 + cyclic shift + window partition
    ln_kernel<<<M_TOK, 256>>>(x, norm1_g, norm1_b, zw, 1);

    // 2. QKV projection: (M,256) @ (256,768) + bias
    gemm_kernel<0><<<dim3(M_TOK / BM, 768 / BN), 256>>>(zw, qkv_w, qkv_b, nullptr, qkv, 768, 256);

    // 3. windowed attention
    attn_kernel<<<dim3(NWIN, NHEADS), 256>>>(qkv, attn_msk, rel_tab, rel_idx, temp, o);

    // 4. proj + window reverse + unshift + residual (from original x)
    gemm_kernel<3><<<dim3(M_TOK / BM, 256 / BN), 256>>>(o, proj_w, proj_b, x, x2, 256, 256);

    // 5. LN2
    ln_kernel<<<M_TOK, 256>>>(x2, norm2_g, norm2_b, hbuf, 0);

    // 6. fc1 + gelu: (M,256) @ (256,1024)
    gemm_kernel<1><<<dim3(M_TOK / BM, 1024 / BN), 256>>>(hbuf, fc1_w, fc1_b, nullptr, fc1, 1024, 256);

    // 7. fc2 + residual: (M,1024) @ (1024,256) -> d_out
    gemm_kernel<2><<<dim3(M_TOK / BM, 256 / BN), 256>>>(fc1, fc2_w, fc2_b, x2, out, 256, 1024);
}

// round 4
// speedup vs baseline: 2.8621x; 2.8621x over previous
#include <cuda_runtime.h>
#include <cuda_bf16.h>
#include <math.h>
#include <stdint.h>

// ---------------------------------------------------------------------------
// SwinTransformerBlock on GB300: warp-MMA (HMMA bf16) GEMMs + SIMT attention
// B=32, H=W=56, C=256, NH=8, hd=32, WS=7, SS=3
// ---------------------------------------------------------------------------

#define M_TOK   100352
#define C_DIM   256
#define NHEADS  8
#define HDIM    32
#define NWIN    2048
#define NSEQ    49

// scratch (device globals; no allocation allowed)
__device__ __nv_bfloat16 g_zw [(size_t)M_TOK * C_DIM];
__device__ __nv_bfloat16 g_qkv[(size_t)M_TOK * 768];
__device__ __nv_bfloat16 g_o  [(size_t)M_TOK * C_DIM];
__device__ float         g_x2 [(size_t)M_TOK * C_DIM];
__device__ __nv_bfloat16 g_h  [(size_t)M_TOK * C_DIM];
__device__ __nv_bfloat16 g_fc1[(size_t)M_TOK * 1024];
// transposed bf16 weights [N, K]
__device__ __nv_bfloat16 g_wqkvT[768 * 256];
__device__ __nv_bfloat16 g_wprojT[256 * 256];
__device__ __nv_bfloat16 g_wfc1T[1024 * 256];
__device__ __nv_bfloat16 g_wfc2T[256 * 1024];

// ---------------------------------------------------------------------------
__device__ __forceinline__ uint32_t smem_u32(const void* p) {
    uint32_t a;
    asm("{ .reg .u64 t; cvta.to.shared.u64 t, %1; cvt.u32.u64 %0, t; }" : "=r"(a) : "l"(p));
    return a;
}
__device__ __forceinline__ void ldsm4(uint32_t* r, uint32_t addr) {
    asm volatile("ldmatrix.sync.aligned.m8n8.x4.shared.b16 {%0,%1,%2,%3}, [%4];"
                 : "=r"(r[0]), "=r"(r[1]), "=r"(r[2]), "=r"(r[3]) : "r"(addr));
}
__device__ __forceinline__ void mma16816(float* c, const uint32_t* a, const uint32_t* b) {
    asm volatile(
        "mma.sync.aligned.m16n8k16.row.col.f32.bf16.bf16.f32 "
        "{%0,%1,%2,%3}, {%4,%5,%6,%7}, {%8,%9}, {%0,%1,%2,%3};"
        : "+f"(c[0]), "+f"(c[1]), "+f"(c[2]), "+f"(c[3])
        : "r"(a[0]), "r"(a[1]), "r"(a[2]), "r"(a[3]), "r"(b[0]), "r"(b[1]));
}
__device__ __forceinline__ uint32_t pack2(float a, float b) {
    __nv_bfloat162 h = __floats2bfloat162_rn(a, b);
    return *(uint32_t*)&h;
}

// ---------------------------------------------------------------------------
// Weight transpose+convert: out[n*K + k] = bf16(in[k*N + n])
// ---------------------------------------------------------------------------
__global__ void wconv_kernel(const float* __restrict__ in, __nv_bfloat16* __restrict__ out,
                             int K, int N)
{
    int id = blockIdx.x * 256 + threadIdx.x;
    if (id >= K * N) return;
    int n = id / K, k = id - n * K;
    out[id] = __float2bfloat16(in[(size_t)k * N + n]);
}

// ---------------------------------------------------------------------------
// LayerNorm (one block per token, 256 threads), bf16 output.
// ---------------------------------------------------------------------------
__global__ void ln_kernel(const float* __restrict__ x,
                          const float* __restrict__ gamma,
                          const float* __restrict__ beta,
                          __nv_bfloat16* __restrict__ out,
                          int shifted)
{
    int t = blockIdx.x;
    int src;
    if (shifted) {
        int wi  = t / NSEQ;
        int pos = t - wi * NSEQ;
        int b    = wi >> 6;
        int wrem = wi & 63;
        int hs = (wrem >> 3) * 7 + pos / 7;
        int ws = (wrem & 7) * 7 + pos % 7;
        int sh = hs + 3; if (sh >= 56) sh -= 56;
        int sw = ws + 3; if (sw >= 56) sw -= 56;
        src = b * 3136 + sh * 56 + sw;
    } else {
        src = t;
    }
    int c = threadIdx.x;
    float v = x[(size_t)src * C_DIM + c];
    float s = v, s2 = v * v;
    #pragma unroll
    for (int off = 16; off; off >>= 1) {
        s  += __shfl_xor_sync(0xffffffffu, s,  off);
        s2 += __shfl_xor_sync(0xffffffffu, s2, off);
    }
    __shared__ float wsum[8], wsum2[8];
    int w = threadIdx.x >> 5, lane = threadIdx.x & 31;
    if (lane == 0) { wsum[w] = s; wsum2[w] = s2; }
    __syncthreads();
    float ts = 0.f, ts2 = 0.f;
    #pragma unroll
    for (int i = 0; i < 8; i++) { ts += wsum[i]; ts2 += wsum2[i]; }
    float mean = ts * (1.f / 256.f);
    float var  = ts2 * (1.f / 256.f) - mean * mean;
    float r = rsqrtf(var + 1e-6f);
    out[(size_t)t * C_DIM + c] = __float2bfloat16((v - mean) * r * gamma[c] + beta[c]);
}

// ---------------------------------------------------------------------------
// Warp-MMA bf16 GEMM: D[M,Nc] = A[M,K] @ Bt[Nc,K]^T (+epilogue)
// Tile 128x128, BK=32, 256 threads (8 warps, 4(M) x 2(N); warp tile 32x64).
// Smem rows padded to 40 bf16 (80B stride -> conflict-free ldmatrix).
// EPI 0: +bias -> bf16                 (qkv)
// EPI 1: gelu(+bias) -> bf16           (fc1)
// EPI 2: +bias +residual[m] -> f32     (fc2 -> d_out)
// EPI 3: +bias, window-reverse scatter, +residual[dst] -> f32  (proj)
// ---------------------------------------------------------------------------
#define KP 40   // padded K stride (bf16 elems)

template<int EPI>
__global__ __launch_bounds__(256) void gemm_bf16(
    const __nv_bfloat16* __restrict__ A,
    const __nv_bfloat16* __restrict__ Bt,
    const float* __restrict__ bias,
    const float* __restrict__ residual,
    void* __restrict__ outv,
    int K, int Nc)
{
    __shared__ __align__(16) __nv_bfloat16 sA[128 * KP];
    __shared__ __align__(16) __nv_bfloat16 sB[128 * KP];
    __shared__ float sbias[128];

    const int tid = threadIdx.x;
    const int lane = tid & 31, wid = tid >> 5;
    const int wm = wid & 3;        // 4 warps in M (32 rows each)
    const int wn = wid >> 2;       // 2 warps in N (64 cols each)
    const int bn = blockIdx.x * 128, bm = blockIdx.y * 128;

    if (tid < 128) sbias[tid] = bias[bn + tid];

    const uint32_t aBase = smem_u32(sA);
    const uint32_t bBase = smem_u32(sB);

    // global tile load indexing: 512 uint4 per tile, 2 per thread per tile
    const int ldr0 = tid >> 2;            // rows 0..63
    const int ldc  = (tid & 3) * 8;       // k offset (bf16)

    // ldmatrix per-thread addresses (byte offsets)
    const uint32_t aRow = (uint32_t)(wm * 32 + (lane & 15));
    const uint32_t aKH  = (lane & 16) ? 8u : 0u;
    const uint32_t bRowBase = (uint32_t)(wn * 64 + (lane & 7) + ((lane & 16) ? 8 : 0));
    const uint32_t bKH  = (lane & 8) ? 8u : 0u;

    float acc[2][8][4];
    #pragma unroll
    for (int i = 0; i < 2; i++)
        #pragma unroll
        for (int j = 0; j < 8; j++)
            #pragma unroll
            for (int t = 0; t < 4; t++) acc[i][j][t] = 0.f;

    const int nk = K >> 5;
    uint4 ra0, ra1, rb0, rb1;
    {   // prologue global load (kc = 0)
        const __nv_bfloat16* Ab = A + (size_t)bm * K;
        const __nv_bfloat16* Bb = Bt + (size_t)bn * K;
        ra0 = *(const uint4*)(Ab + (size_t)ldr0 * K + ldc);
        ra1 = *(const uint4*)(Ab + (size_t)(ldr0 + 64) * K + ldc);
        rb0 = *(const uint4*)(Bb + (size_t)ldr0 * K + ldc);
        rb1 = *(const uint4*)(Bb + (size_t)(ldr0 + 64) * K + ldc);
    }

    for (int kc = 0; kc < nk; kc++) {
        *(uint4*)(sA + ldr0 * KP + ldc)        = ra0;
        *(uint4*)(sA + (ldr0 + 64) * KP + ldc) = ra1;
        *(uint4*)(sB + ldr0 * KP + ldc)        = rb0;
        *(uint4*)(sB + (ldr0 + 64) * KP + ldc) = rb1;
        __syncthreads();

        if (kc + 1 < nk) {
            const __nv_bfloat16* Ab = A + (size_t)bm * K + (kc + 1) * 32;
            const __nv_bfloat16* Bb = Bt + (size_t)bn * K + (kc + 1) * 32;
            ra0 = *(const uint4*)(Ab + (size_t)ldr0 * K + ldc);
            ra1 = *(const uint4*)(Ab + (size_t)(ldr0 + 64) * K + ldc);
            rb0 = *(const uint4*)(Bb + (size_t)ldr0 * K + ldc);
            rb1 = *(const uint4*)(Bb + (size_t)(ldr0 + 64) * K + ldc);
        }

        #pragma unroll
        for (int ks = 0; ks < 2; ks++) {
            uint32_t af[2][4], bf[4][4];
            #pragma unroll
            for (int am = 0; am < 2; am++)
                ldsm4(af[am], aBase + ((aRow + am * 16) * KP + ks * 16 + aKH) * 2);
            #pragma unroll
            for (int g = 0; g < 4; g++)
                ldsm4(bf[g], bBase + ((bRowBase + g * 16) * KP + ks * 16 + bKH) * 2);
            #pragma unroll
            for (int am = 0; am < 2; am++)
                #pragma unroll
                for (int nn = 0; nn < 8; nn++)
                    mma16816(acc[am][nn], af[am], &bf[nn >> 1][(nn & 1) * 2]);
        }
        __syncthreads();
    }

    // ------------------ epilogue ------------------
    const int n0 = bn + wn * 64 + (lane & 3) * 2;
    const int m0 = bm + wm * 32 + (lane >> 2);

    #pragma unroll
    for (int am = 0; am < 2; am++) {
        int mA = m0 + am * 16;        // rows mA and mA+8
        int dstA = mA, dstB = mA + 8;
        if (EPI == 3) {
            #pragma unroll
            for (int h = 0; h < 2; h++) {
                int m = mA + h * 8;
                int wi  = m / NSEQ;
                int pos = m - wi * NSEQ;
                int b    = wi >> 6;
                int wrem = wi & 63;
                int hs = (wrem >> 3) * 7 + pos / 7;
                int ws = (wrem & 7) * 7 + pos % 7;
                int dh = hs + 3; if (dh >= 56) dh -= 56;
                int dw = ws + 3; if (dw >= 56) dw -= 56;
                int d = b * 3136 + dh * 56 + dw;
                if (h == 0) dstA = d; else dstB = d;
            }
        }
        #pragma unroll
        for (int nn = 0; nn < 8; nn++) {
            int col = n0 + nn * 8;
            float b0 = sbias[col - bn], b1 = sbias[col - bn + 1];
            float c0 = acc[am][nn][0] + b0, c1 = acc[am][nn][1] + b1;
            float c2 = acc[am][nn][2] + b0, c3 = acc[am][nn][3] + b1;
            if (EPI == 1) {
                c0 = c0 * 0.5f * (1.f + erff(c0 * 0.70710678118654752f));
                c1 = c1 * 0.5f * (1.f + erff(c1 * 0.70710678118654752f));
                c2 = c2 * 0.5f * (1.f + erff(c2 * 0.70710678118654752f));
                c3 = c3 * 0.5f * (1.f + erff(c3 * 0.70710678118654752f));
            }
            if (EPI == 0 || EPI == 1) {
                __nv_bfloat16* out = (__nv_bfloat16*)outv;
                *(uint32_t*)(out + (size_t)mA * Nc + col)       = pack2(c0, c1);
                *(uint32_t*)(out + (size_t)(mA + 8) * Nc + col) = pack2(c2, c3);
            } else {
                float* out = (float*)outv;
                const float* res = residual;
                float2 r0 = *(const float2*)(res + (size_t)dstA * Nc + col);
                float2 r1 = *(const float2*)(res + (size_t)dstB * Nc + col);
                float2 o0 = make_float2(c0 + r0.x, c1 + r0.y);
                float2 o1 = make_float2(c2 + r1.x, c3 + r1.y);
                *(float2*)(out + (size_t)dstA * Nc + col) = o0;
                *(float2*)(out + (size_t)dstB * Nc + col) = o1;
            }
        }
    }
}

// ---------------------------------------------------------------------------
// Windowed attention (fp32 compute, bf16 I/O): one block per (window, head).
// ---------------------------------------------------------------------------
__global__ void attn_kernel(const __nv_bfloat16* __restrict__ qkv,
                            const float* __restrict__ attn_mask,
                            const float* __restrict__ rel_table,
                            const int*   __restrict__ rel_idx,
                            const float* __restrict__ temperature,
                            __nv_bfloat16* __restrict__ o)
{
    int wi = blockIdx.x;
    int h  = blockIdx.y;
    __shared__ float qs[49][33], ks[49][33], vs[49][33];
    __shared__ float S[49][50];
    int tid = threadIdx.x;

    float scale = expf(temperature[0]);
    const __nv_bfloat16* base = qkv + (size_t)wi * NSEQ * 768 + h * HDIM;

    for (int idx = tid; idx < NSEQ * HDIM; idx += 256) {
        int n = idx >> 5, d = idx & 31;
        const __nv_bfloat16* r = base + n * 768 + d;
        qs[n][d] = __bfloat162float(r[0]);
        ks[n][d] = __bfloat162float(r[256]);
        vs[n][d] = __bfloat162float(r[512]);
    }
    __syncthreads();

    int mask_base = (wi & 63) * (NSEQ * NSEQ);
    for (int idx = tid; idx < NSEQ * NSEQ; idx += 256) {
        int n = idx / NSEQ, m = idx - n * NSEQ;
        float dot = 0.f;
        #pragma unroll
        for (int d = 0; d < HDIM; d++) dot = fmaf(qs[n][d], ks[m][d], dot);
        float s = dot * scale;
        if (n == m) s = -3.402823466e38f;
        s += rel_table[rel_idx[idx] * NHEADS + h];
        s += attn_mask[mask_base + idx];
        S[n][m] = s;
    }
    __syncthreads();

    if (tid < NSEQ) {
        int n = tid;
        float mx = -3.402823466e38f;
        #pragma unroll
        for (int m = 0; m < NSEQ; m++) mx = fmaxf(mx, S[n][m]);
        float sum = 0.f;
        #pragma unroll
        for (int m = 0; m < NSEQ; m++) { float e = expf(S[n][m] - mx); S[n][m] = e; sum += e; }
        float inv = 1.f / sum;
        #pragma unroll
        for (int m = 0; m < NSEQ; m++) S[n][m] *= inv;
    }
    __syncthreads();

    for (int idx = tid; idx < NSEQ * HDIM; idx += 256) {
        int n = idx >> 5, d = idx & 31;
        float a = 0.f;
        #pragma unroll
        for (int m = 0; m < NSEQ; m++) a = fmaf(S[n][m], vs[m][d], a);
        o[(size_t)(wi * NSEQ + n) * C_DIM + h * HDIM + d] = __float2bfloat16(a);
    }
}

// ---------------------------------------------------------------------------
// Launch
// ---------------------------------------------------------------------------
extern "C" void kernel_launch(void* const* d_in, const int* in_sizes, int n_in,
                              void* d_out, int out_size)
{
    const float* x        = (const float*)d_in[0];
    const float* attn_msk = (const float*)d_in[1];
    const float* norm1_g  = (const float*)d_in[2];
    const float* norm1_b  = (const float*)d_in[3];
    const float* qkv_w    = (const float*)d_in[4];
    const float* qkv_b    = (const float*)d_in[5];
    const float* temp     = (const float*)d_in[6];
    const float* rel_tab  = (const float*)d_in[7];
    const float* proj_w   = (const float*)d_in[8];
    const float* proj_b   = (const float*)d_in[9];
    const float* norm2_g  = (const float*)d_in[10];
    const float* norm2_b  = (const float*)d_in[11];
    const float* fc1_w    = (const float*)d_in[12];
    const float* fc1_b    = (const float*)d_in[13];
    const float* fc2_w    = (const float*)d_in[14];
    const float* fc2_b    = (const float*)d_in[15];
    const int*   rel_idx  = (const int*)d_in[16];
    float* out = (float*)d_out;

    __nv_bfloat16 *zw, *qkv, *o, *hbuf, *fc1, *wqkvT, *wprojT, *wfc1T, *wfc2T;
    float *x2;
    cudaGetSymbolAddress((void**)&zw,    g_zw);
    cudaGetSymbolAddress((void**)&qkv,   g_qkv);
    cudaGetSymbolAddress((void**)&o,     g_o);
    cudaGetSymbolAddress((void**)&x2,    g_x2);
    cudaGetSymbolAddress((void**)&hbuf,  g_h);
    cudaGetSymbolAddress((void**)&fc1,   g_fc1);
    cudaGetSymbolAddress((void**)&wqkvT, g_wqkvT);
    cudaGetSymbolAddress((void**)&wprojT,g_wprojT);
    cudaGetSymbolAddress((void**)&wfc1T, g_wfc1T);
    cudaGetSymbolAddress((void**)&wfc2T, g_wfc2T);

    // weight transpose+convert
    wconv_kernel<<<(256 * 768 + 255) / 256, 256>>>(qkv_w,  wqkvT,  256, 768);
    wconv_kernel<<<(256 * 256 + 255) / 256, 256>>>(proj_w, wprojT, 256, 256);
    wconv_kernel<<<(256 * 1024 + 255) / 256, 256>>>(fc1_w, wfc1T,  256, 1024);
    wconv_kernel<<<(1024 * 256 + 255) / 256, 256>>>(fc2_w, wfc2T,  1024, 256);

    // 1. LN1 + cyclic shift + window partition -> bf16
    ln_kernel<<<M_TOK, 256>>>(x, norm1_g, norm1_b, zw, 1);

    // 2. QKV: (M,256)@(256,768) -> bf16
    gemm_bf16<0><<<dim3(6, M_TOK / 128), 256>>>(zw, wqkvT, qkv_b, nullptr, qkv, 256, 768);

    // 3. windowed attention -> bf16
    attn_kernel<<<dim3(NWIN, NHEADS), 256>>>(qkv, attn_msk, rel_tab, rel_idx, temp, o);

    // 4. proj + window-reverse scatter + residual -> f32 x2
    gemm_bf16<3><<<dim3(2, M_TOK / 128), 256>>>(o, wprojT, proj_b, x, x2, 256, 256);

    // 5. LN2 -> bf16
    ln_kernel<<<M_TOK, 256>>>(x2, norm2_g, norm2_b, hbuf, 0);

    // 6. fc1 + gelu: (M,256)@(256,1024) -> bf16
    gemm_bf16<1><<<dim3(8, M_TOK / 128), 256>>>(hbuf, wfc1T, fc1_b, nullptr, fc1, 256, 1024);

    // 7. fc2 + residual: (M,1024)@(1024,256) -> f32 out
    gemm_bf16<2><<<dim3(2, M_TOK / 128), 256>>>(fc1, wfc2T, fc2_b, x2, out, 1024, 256);
}

// round 5
// speedup vs baseline: 3.1451x; 1.0989x over previous
#include <cuda_runtime.h>
#include <cuda_bf16.h>
#include <math.h>
#include <stdint.h>

// ---------------------------------------------------------------------------
// SwinTransformerBlock on GB300: warp-MMA bf16 GEMMs (cp.async pipelined)
// B=32, H=W=56, C=256, NH=8, hd=32, WS=7, SS=3
// ---------------------------------------------------------------------------

#define M_TOK   100352
#define C_DIM   256
#define NHEADS  8
#define HDIM    32
#define NWIN    2048
#define NSEQ    49

__device__ __nv_bfloat16 g_zw [(size_t)M_TOK * C_DIM];
__device__ __nv_bfloat16 g_qkv[(size_t)M_TOK * 768];
__device__ __nv_bfloat16 g_o  [(size_t)M_TOK * C_DIM];
__device__ float         g_x2 [(size_t)M_TOK * C_DIM];
__device__ __nv_bfloat16 g_h  [(size_t)M_TOK * C_DIM];
__device__ __nv_bfloat16 g_fc1[(size_t)M_TOK * 1024];
__device__ __nv_bfloat16 g_wqkvT[768 * 256];
__device__ __nv_bfloat16 g_wprojT[256 * 256];
__device__ __nv_bfloat16 g_wfc1T[1024 * 256];
__device__ __nv_bfloat16 g_wfc2T[256 * 1024];

// ---------------------------------------------------------------------------
__device__ __forceinline__ uint32_t smem_u32(const void* p) {
    uint32_t a;
    asm("{ .reg .u64 t; cvta.to.shared.u64 t, %1; cvt.u32.u64 %0, t; }" : "=r"(a) : "l"(p));
    return a;
}
__device__ __forceinline__ void ldsm4(uint32_t* r, uint32_t addr) {
    asm volatile("ldmatrix.sync.aligned.m8n8.x4.shared.b16 {%0,%1,%2,%3}, [%4];"
                 : "=r"(r[0]), "=r"(r[1]), "=r"(r[2]), "=r"(r[3]) : "r"(addr));
}
__device__ __forceinline__ void mma16816(float* c, const uint32_t* a, const uint32_t* b) {
    asm volatile(
        "mma.sync.aligned.m16n8k16.row.col.f32.bf16.bf16.f32 "
        "{%0,%1,%2,%3}, {%4,%5,%6,%7}, {%8,%9}, {%0,%1,%2,%3};"
        : "+f"(c[0]), "+f"(c[1]), "+f"(c[2]), "+f"(c[3])
        : "r"(a[0]), "r"(a[1]), "r"(a[2]), "r"(a[3]), "r"(b[0]), "r"(b[1]));
}
__device__ __forceinline__ uint32_t pack2(float a, float b) {
    __nv_bfloat162 h = __floats2bfloat162_rn(a, b);
    return *(uint32_t*)&h;
}
#define CP16(dst, src) asm volatile("cp.async.cg.shared.global [%0], [%1], 16;" :: "r"(dst), "l"(src))
#define CP_COMMIT()    asm volatile("cp.async.commit_group;" ::: "memory")
#define CP_WAIT2()     asm volatile("cp.async.wait_group 2;" ::: "memory")

// ---------------------------------------------------------------------------
// Weight transpose+convert: out[n*K + k] = bf16(in[k*N + n])
// ---------------------------------------------------------------------------
__global__ void wconv_kernel(const float* __restrict__ in, __nv_bfloat16* __restrict__ out,
                             int K, int N)
{
    int id = blockIdx.x * 256 + threadIdx.x;
    if (id >= K * N) return;
    int n = id / K, k = id - n * K;
    out[id] = __float2bfloat16(in[(size_t)k * N + n]);
}

// ---------------------------------------------------------------------------
// LayerNorm: warp-per-token. 8 tokens / block (256 threads).
// ---------------------------------------------------------------------------
__global__ __launch_bounds__(256) void ln_kernel(
    const float* __restrict__ x,
    const float* __restrict__ gamma,
    const float* __restrict__ beta,
    __nv_bfloat16* __restrict__ out,
    int shifted)
{
    int wid = threadIdx.x >> 5, lane = threadIdx.x & 31;
    int t = blockIdx.x * 8 + wid;
    int src;
    if (shifted) {
        int wi  = t / NSEQ;
        int pos = t - wi * NSEQ;
        int b    = wi >> 6;
        int wrem = wi & 63;
        int hs = (wrem >> 3) * 7 + pos / 7;
        int ws = (wrem & 7) * 7 + pos % 7;
        int sh = hs + 3; if (sh >= 56) sh -= 56;
        int sw = ws + 3; if (sw >= 56) sw -= 56;
        src = b * 3136 + sh * 56 + sw;
    } else {
        src = t;
    }
    const float* row = x + (size_t)src * C_DIM + lane * 8;
    float4 v0 = *(const float4*)(row);
    float4 v1 = *(const float4*)(row + 4);
    float v[8] = {v0.x, v0.y, v0.z, v0.w, v1.x, v1.y, v1.z, v1.w};
    float s = 0.f, s2 = 0.f;
    #pragma unroll
    for (int i = 0; i < 8; i++) { s += v[i]; s2 += v[i] * v[i]; }
    #pragma unroll
    for (int off = 16; off; off >>= 1) {
        s  += __shfl_xor_sync(0xffffffffu, s,  off);
        s2 += __shfl_xor_sync(0xffffffffu, s2, off);
    }
    float mean = s * (1.f / 256.f);
    float var  = s2 * (1.f / 256.f) - mean * mean;
    float r = rsqrtf(var + 1e-6f);
    const float* g4 = gamma + lane * 8;
    const float* b4 = beta + lane * 8;
    uint32_t o4[4];
    #pragma unroll
    for (int i = 0; i < 4; i++) {
        float a0 = (v[2*i]   - mean) * r * g4[2*i]   + b4[2*i];
        float a1 = (v[2*i+1] - mean) * r * g4[2*i+1] + b4[2*i+1];
        o4[i] = pack2(a0, a1);
    }
    *(uint4*)(out + (size_t)t * C_DIM + lane * 8) = *(uint4*)o4;
}

// ---------------------------------------------------------------------------
// Warp-MMA bf16 GEMM, 4-stage cp.async pipeline.
// Tile 128x128, BK=32, 256 threads (4(M) x 2(N) warps; warp tile 32x64).
// Dynamic smem: 4 stages x (A 128x40 + B 128x40) bf16 = 81920 B.
// ---------------------------------------------------------------------------
#define KP 40
#define STAGE_B (128 * KP * 2 * 2)   // 20480 bytes per stage (A+B)
#define B_OFF   (128 * KP * 2)       // 10240: B after A within a stage

template<int EPI>
__global__ __launch_bounds__(256) void gemm_bf16(
    const __nv_bfloat16* __restrict__ A,
    const __nv_bfloat16* __restrict__ Bt,
    const float* __restrict__ bias,
    const float* __restrict__ residual,
    void* __restrict__ outv,
    int K, int Nc)
{
    extern __shared__ __align__(16) uint8_t smem[];
    __shared__ float sbias[128];

    const int tid = threadIdx.x;
    const int lane = tid & 31, wid = tid >> 5;
    const int wm = wid & 3;
    const int wn = wid >> 2;
    const int bn = blockIdx.x * 128, bm = blockIdx.y * 128;

    if (tid < 128) sbias[tid] = bias[bn + tid];

    const uint32_t sBase = smem_u32(smem);

    const int ldr0 = tid >> 2;            // rows 0..63 (and +64)
    const int ldc  = (tid & 3) * 8;       // k offset (bf16)
    const uint32_t dA0 = (uint32_t)(ldr0 * KP + ldc) * 2;
    const uint32_t dA1 = (uint32_t)((ldr0 + 64) * KP + ldc) * 2;

    const uint32_t aRow = (uint32_t)(wm * 32 + (lane & 15));
    const uint32_t aKH  = (lane & 16) ? 8u : 0u;
    const uint32_t bRowBase = (uint32_t)(wn * 64 + (lane & 7) + ((lane & 16) ? 8 : 0));
    const uint32_t bKH  = (lane & 8) ? 8u : 0u;

    float acc[2][8][4];
    #pragma unroll
    for (int i = 0; i < 2; i++)
        #pragma unroll
        for (int j = 0; j < 8; j++)
            #pragma unroll
            for (int t = 0; t < 4; t++) acc[i][j][t] = 0.f;

    const int nk = K >> 5;

    // prologue: stages 0,1,2
    #pragma unroll
    for (int s = 0; s < 3; s++) {
        uint32_t st = sBase + s * STAGE_B;
        const __nv_bfloat16* Ab = A + (size_t)bm * K + s * 32;
        const __nv_bfloat16* Bb = Bt + (size_t)bn * K + s * 32;
        CP16(st + dA0,         Ab + (size_t)ldr0 * K + ldc);
        CP16(st + dA1,         Ab + (size_t)(ldr0 + 64) * K + ldc);
        CP16(st + B_OFF + dA0, Bb + (size_t)ldr0 * K + ldc);
        CP16(st + B_OFF + dA1, Bb + (size_t)(ldr0 + 64) * K + ldc);
        CP_COMMIT();
    }

    for (int kc = 0; kc < nk; kc++) {
        CP_WAIT2();
        __syncthreads();

        // prefetch stage kc+3 (writes buffer (kc-1)&3, safe after barrier)
        if (kc + 3 < nk) {
            uint32_t st = sBase + ((kc + 3) & 3) * STAGE_B;
            const __nv_bfloat16* Ab = A + (size_t)bm * K + (kc + 3) * 32;
            const __nv_bfloat16* Bb = Bt + (size_t)bn * K + (kc + 3) * 32;
            CP16(st + dA0,         Ab + (size_t)ldr0 * K + ldc);
            CP16(st + dA1,         Ab + (size_t)(ldr0 + 64) * K + ldc);
            CP16(st + B_OFF + dA0, Bb + (size_t)ldr0 * K + ldc);
            CP16(st + B_OFF + dA1, Bb + (size_t)(ldr0 + 64) * K + ldc);
        }
        CP_COMMIT();   // commit even if empty to keep group count in sync

        const uint32_t aS = sBase + (kc & 3) * STAGE_B;
        const uint32_t bS = aS + B_OFF;
        #pragma unroll
        for (int ks = 0; ks < 2; ks++) {
            uint32_t af[2][4], bf[4][4];
            #pragma unroll
            for (int am = 0; am < 2; am++)
                ldsm4(af[am], aS + ((aRow + am * 16) * KP + ks * 16 + aKH) * 2);
            #pragma unroll
            for (int g = 0; g < 4; g++)
                ldsm4(bf[g], bS + ((bRowBase + g * 16) * KP + ks * 16 + bKH) * 2);
            #pragma unroll
            for (int am = 0; am < 2; am++)
                #pragma unroll
                for (int nn = 0; nn < 8; nn++)
                    mma16816(acc[am][nn], af[am], &bf[nn >> 1][(nn & 1) * 2]);
        }
    }

    // ------------------ epilogue ------------------
    const int n0 = bn + wn * 64 + (lane & 3) * 2;
    const int m0 = bm + wm * 32 + (lane >> 2);

    #pragma unroll
    for (int am = 0; am < 2; am++) {
        int mA = m0 + am * 16;
        int dstA = mA, dstB = mA + 8;
        if (EPI == 3) {
            #pragma unroll
            for (int h = 0; h < 2; h++) {
                int m = mA + h * 8;
                int wi  = m / NSEQ;
                int pos = m - wi * NSEQ;
                int b    = wi >> 6;
                int wrem = wi & 63;
                int hs = (wrem >> 3) * 7 + pos / 7;
                int ws = (wrem & 7) * 7 + pos % 7;
                int dh = hs + 3; if (dh >= 56) dh -= 56;
                int dw = ws + 3; if (dw >= 56) dw -= 56;
                int d = b * 3136 + dh * 56 + dw;
                if (h == 0) dstA = d; else dstB = d;
            }
        }
        #pragma unroll
        for (int nn = 0; nn < 8; nn++) {
            int col = n0 + nn * 8;
            float b0 = sbias[col - bn], b1 = sbias[col - bn + 1];
            float c0 = acc[am][nn][0] + b0, c1 = acc[am][nn][1] + b1;
            float c2 = acc[am][nn][2] + b0, c3 = acc[am][nn][3] + b1;
            if (EPI == 1) {
                c0 = c0 * 0.5f * (1.f + erff(c0 * 0.70710678118654752f));
                c1 = c1 * 0.5f * (1.f + erff(c1 * 0.70710678118654752f));
                c2 = c2 * 0.5f * (1.f + erff(c2 * 0.70710678118654752f));
                c3 = c3 * 0.5f * (1.f + erff(c3 * 0.70710678118654752f));
            }
            if (EPI == 0 || EPI == 1) {
                __nv_bfloat16* out = (__nv_bfloat16*)outv;
                *(uint32_t*)(out + (size_t)mA * Nc + col)       = pack2(c0, c1);
                *(uint32_t*)(out + (size_t)(mA + 8) * Nc + col) = pack2(c2, c3);
            } else {
                float* out = (float*)outv;
                float2 r0 = *(const float2*)(residual + (size_t)dstA * Nc + col);
                float2 r1 = *(const float2*)(residual + (size_t)dstB * Nc + col);
                *(float2*)(out + (size_t)dstA * Nc + col) = make_float2(c0 + r0.x, c1 + r0.y);
                *(float2*)(out + (size_t)dstB * Nc + col) = make_float2(c2 + r1.x, c3 + r1.y);
            }
        }
    }
}

// ---------------------------------------------------------------------------
// Windowed attention: one block per (window, head), vectorized bf16 loads.
// ---------------------------------------------------------------------------
__global__ __launch_bounds__(256) void attn_kernel(
    const __nv_bfloat16* __restrict__ qkv,
    const float* __restrict__ attn_mask,
    const float* __restrict__ rel_table,
    const int*   __restrict__ rel_idx,
    const float* __restrict__ temperature,
    __nv_bfloat16* __restrict__ o)
{
    int wi = blockIdx.x;
    int h  = blockIdx.y;
    __shared__ float qs[49][33], ks[49][33], vs[49][33];
    __shared__ float S[49][50];
    int tid = threadIdx.x;

    float scale = expf(temperature[0]);
    const __nv_bfloat16* base = qkv + (size_t)wi * NSEQ * 768 + h * HDIM;

    // 588 uint4 loads: part(q/k/v) x 49 rows x 4 groups of 8 bf16
    for (int idx = tid; idx < 588; idx += 256) {
        int part = idx / 196;
        int rem  = idx - part * 196;
        int n = rem >> 2, cg = (rem & 3) * 8;
        uint4 u = *(const uint4*)(base + (size_t)n * 768 + part * 256 + cg);
        float* dst = (part == 0) ? &qs[n][cg] : (part == 1) ? &ks[n][cg] : &vs[n][cg];
        float2 f0 = __bfloat1622float2(*(__nv_bfloat162*)&u.x);
        float2 f1 = __bfloat1622float2(*(__nv_bfloat162*)&u.y);
        float2 f2 = __bfloat1622float2(*(__nv_bfloat162*)&u.z);
        float2 f3 = __bfloat1622float2(*(__nv_bfloat162*)&u.w);
        dst[0] = f0.x; dst[1] = f0.y; dst[2] = f1.x; dst[3] = f1.y;
        dst[4] = f2.x; dst[5] = f2.y; dst[6] = f3.x; dst[7] = f3.y;
    }
    __syncthreads();

    int mask_base = (wi & 63) * (NSEQ * NSEQ);
    for (int idx = tid; idx < NSEQ * NSEQ; idx += 256) {
        int n = idx / NSEQ, m = idx - n * NSEQ;
        float dot = 0.f;
        #pragma unroll
        for (int d = 0; d < HDIM; d++) dot = fmaf(qs[n][d], ks[m][d], dot);
        float s = dot * scale;
        if (n == m) s = -3.402823466e38f;
        s += rel_table[rel_idx[idx] * NHEADS + h];
        s += attn_mask[mask_base + idx];
        S[n][m] = s;
    }
    __syncthreads();

    if (tid < NSEQ) {
        int n = tid;
        float mx = -3.402823466e38f;
        #pragma unroll
        for (int m = 0; m < NSEQ; m++) mx = fmaxf(mx, S[n][m]);
        float sum = 0.f;
        #pragma unroll
        for (int m = 0; m < NSEQ; m++) { float e = expf(S[n][m] - mx); S[n][m] = e; sum += e; }
        float inv = 1.f / sum;
        #pragma unroll
        for (int m = 0; m < NSEQ; m++) S[n][m] *= inv;
    }
    __syncthreads();

    for (int idx = tid; idx < NSEQ * HDIM; idx += 256) {
        int n = idx >> 5, d = idx & 31;
        float a = 0.f;
        #pragma unroll
        for (int m = 0; m < NSEQ; m++) a = fmaf(S[n][m], vs[m][d], a);
        o[(size_t)(wi * NSEQ + n) * C_DIM + h * HDIM + d] = __float2bfloat16(a);
    }
}

// ---------------------------------------------------------------------------
// Launch
// ---------------------------------------------------------------------------
#define GEMM_SMEM (4 * STAGE_B)

extern "C" void kernel_launch(void* const* d_in, const int* in_sizes, int n_in,
                              void* d_out, int out_size)
{
    const float* x        = (const float*)d_in[0];
    const float* attn_msk = (const float*)d_in[1];
    const float* norm1_g  = (const float*)d_in[2];
    const float* norm1_b  = (const float*)d_in[3];
    const float* qkv_w    = (const float*)d_in[4];
    const float* qkv_b    = (const float*)d_in[5];
    const float* temp     = (const float*)d_in[6];
    const float* rel_tab  = (const float*)d_in[7];
    const float* proj_w   = (const float*)d_in[8];
    const float* proj_b   = (const float*)d_in[9];
    const float* norm2_g  = (const float*)d_in[10];
    const float* norm2_b  = (const float*)d_in[11];
    const float* fc1_w    = (const float*)d_in[12];
    const float* fc1_b    = (const float*)d_in[13];
    const float* fc2_w    = (const float*)d_in[14];
    const float* fc2_b    = (const float*)d_in[15];
    const int*   rel_idx  = (const int*)d_in[16];
    float* out = (float*)d_out;

    __nv_bfloat16 *zw, *qkv, *o, *hbuf, *fc1, *wqkvT, *wprojT, *wfc1T, *wfc2T;
    float *x2;
    cudaGetSymbolAddress((void**)&zw,    g_zw);
    cudaGetSymbolAddress((void**)&qkv,   g_qkv);
    cudaGetSymbolAddress((void**)&o,     g_o);
    cudaGetSymbolAddress((void**)&x2,    g_x2);
    cudaGetSymbolAddress((void**)&hbuf,  g_h);
    cudaGetSymbolAddress((void**)&fc1,   g_fc1);
    cudaGetSymbolAddress((void**)&wqkvT, g_wqkvT);
    cudaGetSymbolAddress((void**)&wprojT,g_wprojT);
    cudaGetSymbolAddress((void**)&wfc1T, g_wfc1T);
    cudaGetSymbolAddress((void**)&wfc2T, g_wfc2T);

    static bool attr_done = false;
    if (!attr_done) {
        cudaFuncSetAttribute(gemm_bf16<0>, cudaFuncAttributeMaxDynamicSharedMemorySize, GEMM_SMEM);
        cudaFuncSetAttribute(gemm_bf16<1>, cudaFuncAttributeMaxDynamicSharedMemorySize, GEMM_SMEM);
        cudaFuncSetAttribute(gemm_bf16<2>, cudaFuncAttributeMaxDynamicSharedMemorySize, GEMM_SMEM);
        cudaFuncSetAttribute(gemm_bf16<3>, cudaFuncAttributeMaxDynamicSharedMemorySize, GEMM_SMEM);
        attr_done = true;
    }

    wconv_kernel<<<(256 * 768 + 255) / 256, 256>>>(qkv_w,  wqkvT,  256, 768);
    wconv_kernel<<<(256 * 256 + 255) / 256, 256>>>(proj_w, wprojT, 256, 256);
    wconv_kernel<<<(256 * 1024 + 255) / 256, 256>>>(fc1_w, wfc1T,  256, 1024);
    wconv_kernel<<<(1024 * 256 + 255) / 256, 256>>>(fc2_w, wfc2T,  1024, 256);

    // 1. LN1 + cyclic shift + window partition -> bf16
    ln_kernel<<<M_TOK / 8, 256>>>(x, norm1_g, norm1_b, zw, 1);

    // 2. QKV: (M,256)@(256,768) -> bf16
    gemm_bf16<0><<<dim3(6, M_TOK / 128), 256, GEMM_SMEM>>>(zw, wqkvT, qkv_b, nullptr, qkv, 256, 768);

    // 3. windowed attention -> bf16
    attn_kernel<<<dim3(NWIN, NHEADS), 256>>>(qkv, attn_msk, rel_tab, rel_idx, temp, o);

    // 4. proj + window-reverse scatter + residual -> f32 x2
    gemm_bf16<3><<<dim3(2, M_TOK / 128), 256, GEMM_SMEM>>>(o, wprojT, proj_b, x, x2, 256, 256);

    // 5. LN2 -> bf16
    ln_kernel<<<M_TOK / 8, 256>>>(x2, norm2_g, norm2_b, hbuf, 0);

    // 6. fc1 + gelu: (M,256)@(256,1024) -> bf16
    gemm_bf16<1><<<dim3(8, M_TOK / 128), 256, GEMM_SMEM>>>(hbuf, wfc1T, fc1_b, nullptr, fc1, 256, 1024);

    // 7. fc2 + residual: (M,1024)@(1024,256) -> f32 out
    gemm_bf16<2><<<dim3(2, M_TOK / 128), 256, GEMM_SMEM>>>(fc1, wfc2T, fc2_b, x2, out, 1024, 256);
}

// round 6
// speedup vs baseline: 3.3443x; 1.0633x over previous
#include <cuda_runtime.h>
#include <cuda_bf16.h>
#include <math.h>
#include <stdint.h>

// ---------------------------------------------------------------------------
// SwinTransformerBlock on GB300: warp-MMA bf16 GEMMs (64x64 warp tiles)
// B=32, H=W=56, C=256, NH=8, hd=32, WS=7, SS=3
// ---------------------------------------------------------------------------

#define M_TOK   100352
#define C_DIM   256
#define NHEADS  8
#define HDIM    32
#define NWIN    2048
#define NSEQ    49

__device__ __nv_bfloat16 g_zw [(size_t)M_TOK * C_DIM];
__device__ __nv_bfloat16 g_qkv[(size_t)M_TOK * 768];
__device__ __nv_bfloat16 g_o  [(size_t)M_TOK * C_DIM];
__device__ float         g_x2 [(size_t)M_TOK * C_DIM];
__device__ __nv_bfloat16 g_h  [(size_t)M_TOK * C_DIM];
__device__ __nv_bfloat16 g_fc1[(size_t)M_TOK * 1024];
__device__ __nv_bfloat16 g_wqkvT[768 * 256];
__device__ __nv_bfloat16 g_wprojT[256 * 256];
__device__ __nv_bfloat16 g_wfc1T[1024 * 256];
__device__ __nv_bfloat16 g_wfc2T[256 * 1024];
__device__ float g_battn[NHEADS * NSEQ * NSEQ];   // precomputed rel-pos bias

// ---------------------------------------------------------------------------
__device__ __forceinline__ uint32_t smem_u32(const void* p) {
    uint32_t a;
    asm("{ .reg .u64 t; cvta.to.shared.u64 t, %1; cvt.u32.u64 %0, t; }" : "=r"(a) : "l"(p));
    return a;
}
__device__ __forceinline__ void ldsm4(uint32_t* r, uint32_t addr) {
    asm volatile("ldmatrix.sync.aligned.m8n8.x4.shared.b16 {%0,%1,%2,%3}, [%4];"
                 : "=r"(r[0]), "=r"(r[1]), "=r"(r[2]), "=r"(r[3]) : "r"(addr));
}
__device__ __forceinline__ void mma16816(float* c, const uint32_t* a, const uint32_t* b) {
    asm volatile(
        "mma.sync.aligned.m16n8k16.row.col.f32.bf16.bf16.f32 "
        "{%0,%1,%2,%3}, {%4,%5,%6,%7}, {%8,%9}, {%0,%1,%2,%3};"
        : "+f"(c[0]), "+f"(c[1]), "+f"(c[2]), "+f"(c[3])
        : "r"(a[0]), "r"(a[1]), "r"(a[2]), "r"(a[3]), "r"(b[0]), "r"(b[1]));
}
__device__ __forceinline__ uint32_t pack2(float a, float b) {
    __nv_bfloat162 h = __floats2bfloat162_rn(a, b);
    return *(uint32_t*)&h;
}
#define CP16(dst, src) asm volatile("cp.async.cg.shared.global [%0], [%1], 16;" :: "r"(dst), "l"(src))
#define CP_COMMIT()    asm volatile("cp.async.commit_group;" ::: "memory")
#define CP_WAIT2()     asm volatile("cp.async.wait_group 2;" ::: "memory")

// ---------------------------------------------------------------------------
__global__ void wconv_kernel(const float* __restrict__ in, __nv_bfloat16* __restrict__ out,
                             int K, int N)
{
    int id = blockIdx.x * 256 + threadIdx.x;
    if (id >= K * N) return;
    int n = id / K, k = id - n * K;
    out[id] = __float2bfloat16(in[(size_t)k * N + n]);
}

// precompute bias[h][n*49+m] = rel_table[rel_idx[n*49+m]*8 + h]
__global__ void bias_kernel(const float* __restrict__ rel_table,
                            const int* __restrict__ rel_idx,
                            float* __restrict__ out)
{
    int idx = blockIdx.x * 256 + threadIdx.x;
    if (idx >= NHEADS * NSEQ * NSEQ) return;
    int h = idx / (NSEQ * NSEQ), nm = idx % (NSEQ * NSEQ);
    out[idx] = rel_table[rel_idx[nm] * NHEADS + h];
}

// ---------------------------------------------------------------------------
// LayerNorm: warp-per-token. 8 tokens / block.
// ---------------------------------------------------------------------------
__global__ __launch_bounds__(256) void ln_kernel(
    const float* __restrict__ x,
    const float* __restrict__ gamma,
    const float* __restrict__ beta,
    __nv_bfloat16* __restrict__ out,
    int shifted)
{
    int wid = threadIdx.x >> 5, lane = threadIdx.x & 31;
    int t = blockIdx.x * 8 + wid;
    int src;
    if (shifted) {
        int wi  = t / NSEQ;
        int pos = t - wi * NSEQ;
        int b    = wi >> 6;
        int wrem = wi & 63;
        int hs = (wrem >> 3) * 7 + pos / 7;
        int ws = (wrem & 7) * 7 + pos % 7;
        int sh = hs + 3; if (sh >= 56) sh -= 56;
        int sw = ws + 3; if (sw >= 56) sw -= 56;
        src = b * 3136 + sh * 56 + sw;
    } else {
        src = t;
    }
    const float* row = x + (size_t)src * C_DIM + lane * 8;
    float4 v0 = *(const float4*)(row);
    float4 v1 = *(const float4*)(row + 4);
    float v[8] = {v0.x, v0.y, v0.z, v0.w, v1.x, v1.y, v1.z, v1.w};
    float s = 0.f, s2 = 0.f;
    #pragma unroll
    for (int i = 0; i < 8; i++) { s += v[i]; s2 += v[i] * v[i]; }
    #pragma unroll
    for (int off = 16; off; off >>= 1) {
        s  += __shfl_xor_sync(0xffffffffu, s,  off);
        s2 += __shfl_xor_sync(0xffffffffu, s2, off);
    }
    float mean = s * (1.f / 256.f);
    float var  = s2 * (1.f / 256.f) - mean * mean;
    float r = rsqrtf(var + 1e-6f);
    const float* g4 = gamma + lane * 8;
    const float* b4 = beta + lane * 8;
    uint32_t o4[4];
    #pragma unroll
    for (int i = 0; i < 4; i++) {
        float a0 = (v[2*i]   - mean) * r * g4[2*i]   + b4[2*i];
        float a1 = (v[2*i+1] - mean) * r * g4[2*i+1] + b4[2*i+1];
        o4[i] = pack2(a0, a1);
    }
    *(uint4*)(out + (size_t)t * C_DIM + lane * 8) = *(uint4*)o4;
}

// ---------------------------------------------------------------------------
// Warp-MMA bf16 GEMM: tile 128x128, BK=32, 128 threads.
// 4 warps (2M x 2N), warp tile 64x64: 1.0 ldmatrix-wavefront per MMA.
// 4-stage cp.async pipeline.
// ---------------------------------------------------------------------------
#define KP 40
#define STAGE_B (128 * KP * 2 * 2)   // 20480 bytes/stage (A+B)
#define B_OFF   (128 * KP * 2)

template<int EPI>
__global__ __launch_bounds__(128) void gemm_bf16(
    const __nv_bfloat16* __restrict__ A,
    const __nv_bfloat16* __restrict__ Bt,
    const float* __restrict__ bias,
    const float* __restrict__ residual,
    void* __restrict__ outv,
    int K, int Nc)
{
    extern __shared__ __align__(16) uint8_t smem[];
    __shared__ float sbias[128];

    const int tid = threadIdx.x;
    const int lane = tid & 31, wid = tid >> 5;
    const int wm = wid & 1;        // 2 warps in M (64 rows each)
    const int wn = wid >> 1;       // 2 warps in N (64 cols each)
    const int bn = blockIdx.x * 128, bm = blockIdx.y * 128;

    sbias[tid] = bias[bn + tid];

    const uint32_t sBase = smem_u32(smem);

    // global->smem: 128 threads, each loads 4 rows (stride 32) x 16B for A and B
    const int ldr0 = tid >> 2;            // rows 0..31
    const int ldc  = (tid & 3) * 8;       // k offset (bf16)

    // ldmatrix addressing
    const uint32_t aRowB = (uint32_t)(wm * 64 + (lane & 15));
    const uint32_t aKH   = (lane & 16) ? 8u : 0u;
    const uint32_t bRowB = (uint32_t)(wn * 64 + (lane & 7) + ((lane & 16) ? 8 : 0));
    const uint32_t bKH   = (lane & 8) ? 8u : 0u;

    float acc[4][8][4];
    #pragma unroll
    for (int i = 0; i < 4; i++)
        #pragma unroll
        for (int j = 0; j < 8; j++)
            #pragma unroll
            for (int t = 0; t < 4; t++) acc[i][j][t] = 0.f;

    const int nk = K >> 5;

    // prologue: stages 0,1,2
    #pragma unroll
    for (int s = 0; s < 3; s++) {
        uint32_t st = sBase + s * STAGE_B;
        const __nv_bfloat16* Ab = A + (size_t)bm * K + s * 32;
        const __nv_bfloat16* Bb = Bt + (size_t)bn * K + s * 32;
        #pragma unroll
        for (int j = 0; j < 4; j++) {
            int r = ldr0 + j * 32;
            CP16(st + (uint32_t)(r * KP + ldc) * 2,         Ab + (size_t)r * K + ldc);
            CP16(st + B_OFF + (uint32_t)(r * KP + ldc) * 2, Bb + (size_t)r * K + ldc);
        }
        CP_COMMIT();
    }

    for (int kc = 0; kc < nk; kc++) {
        CP_WAIT2();
        __syncthreads();

        if (kc + 3 < nk) {
            uint32_t st = sBase + ((kc + 3) & 3) * STAGE_B;
            const __nv_bfloat16* Ab = A + (size_t)bm * K + (kc + 3) * 32;
            const __nv_bfloat16* Bb = Bt + (size_t)bn * K + (kc + 3) * 32;
            #pragma unroll
            for (int j = 0; j < 4; j++) {
                int r = ldr0 + j * 32;
                CP16(st + (uint32_t)(r * KP + ldc) * 2,         Ab + (size_t)r * K + ldc);
                CP16(st + B_OFF + (uint32_t)(r * KP + ldc) * 2, Bb + (size_t)r * K + ldc);
            }
        }
        CP_COMMIT();

        const uint32_t aS = sBase + (kc & 3) * STAGE_B;
        const uint32_t bS = aS + B_OFF;
        #pragma unroll
        for (int ks = 0; ks < 2; ks++) {
            uint32_t af[4][4], bf[4][4];
            #pragma unroll
            for (int am = 0; am < 4; am++)
                ldsm4(af[am], aS + ((aRowB + am * 16) * KP + ks * 16 + aKH) * 2);
            #pragma unroll
            for (int g = 0; g < 4; g++)
                ldsm4(bf[g], bS + ((bRowB + g * 16) * KP + ks * 16 + bKH) * 2);
            #pragma unroll
            for (int am = 0; am < 4; am++)
                #pragma unroll
                for (int nn = 0; nn < 8; nn++)
                    mma16816(acc[am][nn], af[am], &bf[nn >> 1][(nn & 1) * 2]);
        }
        __syncthreads();
    }

    // ------------------ epilogue ------------------
    const int n0 = bn + wn * 64 + (lane & 3) * 2;
    const int m0 = bm + wm * 64 + (lane >> 2);

    #pragma unroll
    for (int am = 0; am < 4; am++) {
        int mA = m0 + am * 16;
        int dstA = mA, dstB = mA + 8;
        if (EPI == 3) {
            #pragma unroll
            for (int h = 0; h < 2; h++) {
                int m = mA + h * 8;
                int wi  = m / NSEQ;
                int pos = m - wi * NSEQ;
                int b    = wi >> 6;
                int wrem = wi & 63;
                int hs = (wrem >> 3) * 7 + pos / 7;
                int ws = (wrem & 7) * 7 + pos % 7;
                int dh = hs + 3; if (dh >= 56) dh -= 56;
                int dw = ws + 3; if (dw >= 56) dw -= 56;
                int d = b * 3136 + dh * 56 + dw;
                if (h == 0) dstA = d; else dstB = d;
            }
        }
        #pragma unroll
        for (int nn = 0; nn < 8; nn++) {
            int col = n0 + nn * 8;
            float b0 = sbias[col - bn], b1 = sbias[col - bn + 1];
            float c0 = acc[am][nn][0] + b0, c1 = acc[am][nn][1] + b1;
            float c2 = acc[am][nn][2] + b0, c3 = acc[am][nn][3] + b1;
            if (EPI == 1) {
                c0 = c0 * 0.5f * (1.f + erff(c0 * 0.70710678118654752f));
                c1 = c1 * 0.5f * (1.f + erff(c1 * 0.70710678118654752f));
                c2 = c2 * 0.5f * (1.f + erff(c2 * 0.70710678118654752f));
                c3 = c3 * 0.5f * (1.f + erff(c3 * 0.70710678118654752f));
            }
            if (EPI == 0 || EPI == 1) {
                __nv_bfloat16* out = (__nv_bfloat16*)outv;
                *(uint32_t*)(out + (size_t)mA * Nc + col)       = pack2(c0, c1);
                *(uint32_t*)(out + (size_t)(mA + 8) * Nc + col) = pack2(c2, c3);
            } else {
                float* out = (float*)outv;
                float2 r0 = *(const float2*)(residual + (size_t)dstA * Nc + col);
                float2 r1 = *(const float2*)(residual + (size_t)dstB * Nc + col);
                *(float2*)(out + (size_t)dstA * Nc + col) = make_float2(c0 + r0.x, c1 + r0.y);
                *(float2*)(out + (size_t)dstB * Nc + col) = make_float2(c2 + r1.x, c3 + r1.y);
            }
        }
    }
}

// ---------------------------------------------------------------------------
// Windowed attention: one block per (window, head).
// ---------------------------------------------------------------------------
__global__ __launch_bounds__(256) void attn_kernel(
    const __nv_bfloat16* __restrict__ qkv,
    const float* __restrict__ attn_mask,
    const float* __restrict__ battn,
    const float* __restrict__ temperature,
    __nv_bfloat16* __restrict__ o)
{
    int wi = blockIdx.x;
    int h  = blockIdx.y;
    __shared__ float qs[49][33], ks[49][33], vs[49][33];
    __shared__ float S[49][50];
    int tid = threadIdx.x;

    float scale = expf(temperature[0]);
    const __nv_bfloat16* base = qkv + (size_t)wi * NSEQ * 768 + h * HDIM;

    for (int idx = tid; idx < 588; idx += 256) {
        int part = idx / 196;
        int rem  = idx - part * 196;
        int n = rem >> 2, cg = (rem & 3) * 8;
        uint4 u = *(const uint4*)(base + (size_t)n * 768 + part * 256 + cg);
        float* dst = (part == 0) ? &qs[n][cg] : (part == 1) ? &ks[n][cg] : &vs[n][cg];
        float2 f0 = __bfloat1622float2(*(__nv_bfloat162*)&u.x);
        float2 f1 = __bfloat1622float2(*(__nv_bfloat162*)&u.y);
        float2 f2 = __bfloat1622float2(*(__nv_bfloat162*)&u.z);
        float2 f3 = __bfloat1622float2(*(__nv_bfloat162*)&u.w);
        dst[0] = f0.x; dst[1] = f0.y; dst[2] = f1.x; dst[3] = f1.y;
        dst[4] = f2.x; dst[5] = f2.y; dst[6] = f3.x; dst[7] = f3.y;
    }
    __syncthreads();

    int mask_base = (wi & 63) * (NSEQ * NSEQ);
    const float* bia = battn + h * (NSEQ * NSEQ);
    for (int idx = tid; idx < NSEQ * NSEQ; idx += 256) {
        int n = idx / NSEQ, m = idx - n * NSEQ;
        float dot = 0.f;
        #pragma unroll
        for (int d = 0; d < HDIM; d++) dot = fmaf(qs[n][d], ks[m][d], dot);
        float s = dot * scale;
        if (n == m) s = -3.402823466e38f;
        s += bia[idx];
        s += attn_mask[mask_base + idx];
        S[n][m] = s;
    }
    __syncthreads();

    if (tid < NSEQ) {
        int n = tid;
        float mx = -3.402823466e38f;
        #pragma unroll
        for (int m = 0; m < NSEQ; m++) mx = fmaxf(mx, S[n][m]);
        float sum = 0.f;
        #pragma unroll
        for (int m = 0; m < NSEQ; m++) { float e = expf(S[n][m] - mx); S[n][m] = e; sum += e; }
        float inv = 1.f / sum;
        #pragma unroll
        for (int m = 0; m < NSEQ; m++) S[n][m] *= inv;
    }
    __syncthreads();

    for (int idx = tid; idx < NSEQ * HDIM; idx += 256) {
        int n = idx >> 5, d = idx & 31;
        float a = 0.f;
        #pragma unroll
        for (int m = 0; m < NSEQ; m++) a = fmaf(S[n][m], vs[m][d], a);
        o[(size_t)(wi * NSEQ + n) * C_DIM + h * HDIM + d] = __float2bfloat16(a);
    }
}

// ---------------------------------------------------------------------------
#define GEMM_SMEM (4 * STAGE_B)

extern "C" void kernel_launch(void* const* d_in, const int* in_sizes, int n_in,
                              void* d_out, int out_size)
{
    const float* x        = (const float*)d_in[0];
    const float* attn_msk = (const float*)d_in[1];
    const float* norm1_g  = (const float*)d_in[2];
    const float* norm1_b  = (const float*)d_in[3];
    const float* qkv_w    = (const float*)d_in[4];
    const float* qkv_b    = (const float*)d_in[5];
    const float* temp     = (const float*)d_in[6];
    const float* rel_tab  = (const float*)d_in[7];
    const float* proj_w   = (const float*)d_in[8];
    const float* proj_b   = (const float*)d_in[9];
    const float* norm2_g  = (const float*)d_in[10];
    const float* norm2_b  = (const float*)d_in[11];
    const float* fc1_w    = (const float*)d_in[12];
    const float* fc1_b    = (const float*)d_in[13];
    const float* fc2_w    = (const float*)d_in[14];
    const float* fc2_b    = (const float*)d_in[15];
    const int*   rel_idx  = (const int*)d_in[16];
    float* out = (float*)d_out;

    __nv_bfloat16 *zw, *qkv, *o, *hbuf, *fc1, *wqkvT, *wprojT, *wfc1T, *wfc2T;
    float *x2, *battn;
    cudaGetSymbolAddress((void**)&zw,    g_zw);
    cudaGetSymbolAddress((void**)&qkv,   g_qkv);
    cudaGetSymbolAddress((void**)&o,     g_o);
    cudaGetSymbolAddress((void**)&x2,    g_x2);
    cudaGetSymbolAddress((void**)&hbuf,  g_h);
    cudaGetSymbolAddress((void**)&fc1,   g_fc1);
    cudaGetSymbolAddress((void**)&wqkvT, g_wqkvT);
    cudaGetSymbolAddress((void**)&wprojT,g_wprojT);
    cudaGetSymbolAddress((void**)&wfc1T, g_wfc1T);
    cudaGetSymbolAddress((void**)&wfc2T, g_wfc2T);
    cudaGetSymbolAddress((void**)&battn, g_battn);

    static bool attr_done = false;
    if (!attr_done) {
        cudaFuncSetAttribute(gemm_bf16<0>, cudaFuncAttributeMaxDynamicSharedMemorySize, GEMM_SMEM);
        cudaFuncSetAttribute(gemm_bf16<1>, cudaFuncAttributeMaxDynamicSharedMemorySize, GEMM_SMEM);
        cudaFuncSetAttribute(gemm_bf16<2>, cudaFuncAttributeMaxDynamicSharedMemorySize, GEMM_SMEM);
        cudaFuncSetAttribute(gemm_bf16<3>, cudaFuncAttributeMaxDynamicSharedMemorySize, GEMM_SMEM);
        attr_done = true;
    }

    wconv_kernel<<<(256 * 768 + 255) / 256, 256>>>(qkv_w,  wqkvT,  256, 768);
    wconv_kernel<<<(256 * 256 + 255) / 256, 256>>>(proj_w, wprojT, 256, 256);
    wconv_kernel<<<(256 * 1024 + 255) / 256, 256>>>(fc1_w, wfc1T,  256, 1024);
    wconv_kernel<<<(1024 * 256 + 255) / 256, 256>>>(fc2_w, wfc2T,  1024, 256);
    bias_kernel<<<(NHEADS * NSEQ * NSEQ + 255) / 256, 256>>>(rel_tab, rel_idx, battn);

    // 1. LN1 + cyclic shift + window partition -> bf16
    ln_kernel<<<M_TOK / 8, 256>>>(x, norm1_g, norm1_b, zw, 1);

    // 2. QKV: (M,256)@(256,768) -> bf16
    gemm_bf16<0><<<dim3(6, M_TOK / 128), 128, GEMM_SMEM>>>(zw, wqkvT, qkv_b, nullptr, qkv, 256, 768);

    // 3. windowed attention -> bf16
    attn_kernel<<<dim3(NWIN, NHEADS), 256>>>(qkv, attn_msk, battn, temp, o);

    // 4. proj + window-reverse scatter + residual -> f32 x2
    gemm_bf16<3><<<dim3(2, M_TOK / 128), 128, GEMM_SMEM>>>(o, wprojT, proj_b, x, x2, 256, 256);

    // 5. LN2 -> bf16
    ln_kernel<<<M_TOK / 8, 256>>>(x2, norm2_g, norm2_b, hbuf, 0);

    // 6. fc1 + gelu: (M,256)@(256,1024) -> bf16
    gemm_bf16<1><<<dim3(8, M_TOK / 128), 128, GEMM_SMEM>>>(hbuf, wfc1T, fc1_b, nullptr, fc1, 256, 1024);

    // 7. fc2 + residual: (M,1024)@(1024,256) -> f32 out
    gemm_bf16<2><<<dim3(2, M_TOK / 128), 128, GEMM_SMEM>>>(fc1, wfc2T, fc2_b, x2, out, 1024, 256);
}